// round 5
// baseline (speedup 1.0000x reference)
#include <cuda_runtime.h>
#include <cuda_bf16.h>
#include <math.h>
#include <stdint.h>

#define TB 4
#define TT 1024
#define TC 1024
#define TH 16
#define THD 64
#define MR (TB*TT)          // 4096 rows
#define N3C (3*TC)          // 3072

// ---------------- scratch (allocation-free rule: device globals) -----------
static __device__ float g_qkv[(size_t)MR * N3C];     // 48 MB
static __device__ __nv_bfloat16 g_xhi[(size_t)MR * TC];
static __device__ __nv_bfloat16 g_xlo[(size_t)MR * TC];
static __device__ __nv_bfloat16 g_wqkv_hi[(size_t)N3C * TC];   // W^T [3072,1024]
static __device__ __nv_bfloat16 g_wqkv_lo[(size_t)N3C * TC];
static __device__ __nv_bfloat16 g_wpr_hi[(size_t)TC * TC];     // W^T [1024,1024]
static __device__ __nv_bfloat16 g_wpr_lo[(size_t)TC * TC];
static __device__ __nv_bfloat16 g_yhi[(size_t)MR * TC];
static __device__ __nv_bfloat16 g_ylo[(size_t)MR * TC];

// ---------------- PTX helpers (baseline ISA only) ---------------------------
__device__ __forceinline__ uint32_t smem_u32(const void* p) {
    uint32_t a;
    asm("{ .reg .u64 t; cvta.to.shared.u64 t, %1; cvt.u32.u64 %0, t; }" : "=r"(a) : "l"(p));
    return a;
}
__device__ __forceinline__ void ldsm_x4(uint32_t (&r)[4], uint32_t addr) {
    asm volatile("ldmatrix.sync.aligned.m8n8.x4.shared.b16 {%0,%1,%2,%3}, [%4];"
        : "=r"(r[0]), "=r"(r[1]), "=r"(r[2]), "=r"(r[3]) : "r"(addr));
}
__device__ __forceinline__ void mma_bf16(float (&d)[4], const uint32_t (&a)[4],
                                         uint32_t b0, uint32_t b1) {
    asm volatile("mma.sync.aligned.m16n8k16.row.col.f32.bf16.bf16.f32 "
        "{%0,%1,%2,%3}, {%4,%5,%6,%7}, {%8,%9}, {%0,%1,%2,%3};"
        : "+f"(d[0]), "+f"(d[1]), "+f"(d[2]), "+f"(d[3])
        : "r"(a[0]), "r"(a[1]), "r"(a[2]), "r"(a[3]), "r"(b0), "r"(b1));
}
__device__ __forceinline__ void cp_async16(uint32_t dst, const void* src) {
    asm volatile("cp.async.cg.shared.global [%0], [%1], 16;" :: "r"(dst), "l"(src) : "memory");
}
#define CP_COMMIT() asm volatile("cp.async.commit_group;" ::: "memory")
#define CP_WAIT2()  asm volatile("cp.async.wait_group 2;" ::: "memory")
#define CP_WAIT1()  asm volatile("cp.async.wait_group 1;" ::: "memory")
#define CP_WAIT0()  asm volatile("cp.async.wait_group 0;" ::: "memory")

// smem tile geometry: 128 rows x 24 bf16 (16 data + 8 pad -> conflict-free LDSM)
#define TROW 24
#define TILE_ELEMS (128*TROW)           // 3072 bf16
#define STAGE_ELEMS (4*TILE_ELEMS)      // Ah,Al,Bh,Bl = 12288 bf16
#define NSTAGE 4
#define GEMM_SMEM (NSTAGE*STAGE_ELEMS*2)  // 98304 bytes

// ---------------------------------------------------------------------------
// Split-bf16 tensor-core GEMM, 4-stage cp.async pipeline, single sync/iter:
//   C[M,N](fp32) = (Ahi+Alo) @ (Bhi+Blo)^T ; 3 products (lo*lo dropped).
// CTA 128x128, BK=16, 8 warps (4m x 2n), warp tile 32x64, mma.m16n8k16.
// ---------------------------------------------------------------------------
__global__ __launch_bounds__(256) void gemm_mma(
    const __nv_bfloat16* __restrict__ Ahi, const __nv_bfloat16* __restrict__ Alo,
    const __nv_bfloat16* __restrict__ Bhi, const __nv_bfloat16* __restrict__ Blo,
    float* __restrict__ C, int M, int N, int K)
{
    extern __shared__ __nv_bfloat16 smem[];   // NSTAGE stages x 4 tiles

    const int t = threadIdx.x, lane = t & 31, wid = t >> 5;
    const int wm = wid & 3, wn = wid >> 2;
    const int bm = blockIdx.y * 128, bn = blockIdx.x * 128;

    float acc[2][8][4];
    #pragma unroll
    for (int i = 0; i < 2; i++)
        #pragma unroll
        for (int j = 0; j < 8; j++)
            #pragma unroll
            for (int k = 0; k < 4; k++) acc[i][j][k] = 0.f;

    // staging: 256 chunks (16B) per tile -> 1 chunk per thread per tile
    const int sr = t >> 1, scc = (t & 1) * 8;
    const __nv_bfloat16* gptr[4];
    gptr[0] = Ahi + (size_t)(bm + sr) * K + scc;
    gptr[1] = Alo + (size_t)(bm + sr) * K + scc;
    gptr[2] = Bhi + (size_t)(bn + sr) * K + scc;
    gptr[3] = Blo + (size_t)(bn + sr) * K + scc;
    uint32_t sdst[4];
    #pragma unroll
    for (int w = 0; w < 4; w++)
        sdst[w] = smem_u32(smem + w * TILE_ELEMS + sr * TROW + scc);
    const uint32_t stage_bytes = STAGE_ELEMS * 2;

    // LDSM lane addressing
    const int a_row = wm * 32 + (lane & 15);
    const int a_coff = (lane >> 4) * 8;
    const int b_row = wn * 64 + (lane & 7) + ((lane >> 4) & 1) * 8;
    const int b_coff = ((lane >> 3) & 1) * 8;

    const int niter = K >> 4;   // K/16

    // prologue: issue stages 0..2
    #pragma unroll
    for (int s = 0; s < NSTAGE - 1; s++) {
        const uint32_t soff = s * stage_bytes;
        #pragma unroll
        for (int w = 0; w < 4; w++)
            cp_async16(sdst[w] + soff, gptr[w] + (s << 4));
        CP_COMMIT();
    }

    for (int it = 0; it < niter; it++) {
        const int rem = niter - 1 - it;
        if (rem >= 2) CP_WAIT2(); else if (rem == 1) CP_WAIT1(); else CP_WAIT0();
        __syncthreads();

        // issue stage it+3
        if (it + NSTAGE - 1 < niter) {
            const uint32_t soff = ((it + NSTAGE - 1) & (NSTAGE - 1)) * stage_bytes;
            const int kn = (it + NSTAGE - 1) << 4;
            #pragma unroll
            for (int w = 0; w < 4; w++)
                cp_async16(sdst[w] + soff, gptr[w] + kn);
            CP_COMMIT();
        }

        const __nv_bfloat16* bs = smem + (it & (NSTAGE - 1)) * STAGE_ELEMS;

        uint32_t ah[2][4], al[2][4];
        #pragma unroll
        for (int mt = 0; mt < 2; mt++) {
            ldsm_x4(ah[mt], smem_u32(bs + (a_row + mt*16) * TROW + a_coff));
            ldsm_x4(al[mt], smem_u32(bs + TILE_ELEMS + (a_row + mt*16) * TROW + a_coff));
        }

        // B fragment ping-pong: prefetch np+1 while doing mma on np
        uint32_t bh[2][4], bl[2][4];
        ldsm_x4(bh[0], smem_u32(bs + 2*TILE_ELEMS + b_row * TROW + b_coff));
        ldsm_x4(bl[0], smem_u32(bs + 3*TILE_ELEMS + b_row * TROW + b_coff));
        #pragma unroll
        for (int np = 0; np < 4; np++) {
            const int cur = np & 1, nxt = cur ^ 1;
            if (np < 3) {
                ldsm_x4(bh[nxt], smem_u32(bs + 2*TILE_ELEMS + (b_row + (np+1)*16) * TROW + b_coff));
                ldsm_x4(bl[nxt], smem_u32(bs + 3*TILE_ELEMS + (b_row + (np+1)*16) * TROW + b_coff));
            }
            #pragma unroll
            for (int half = 0; half < 2; half++) {
                const int nt = np * 2 + half;
                #pragma unroll
                for (int mt = 0; mt < 2; mt++) {
                    mma_bf16(acc[mt][nt], ah[mt], bh[cur][2*half], bh[cur][2*half+1]);
                    mma_bf16(acc[mt][nt], ah[mt], bl[cur][2*half], bl[cur][2*half+1]);
                    mma_bf16(acc[mt][nt], al[mt], bh[cur][2*half], bh[cur][2*half+1]);
                }
            }
        }
    }

    // epilogue: D frag lane l -> rows (g, g+8), cols (2t, 2t+1)
    const int g = lane >> 2, tq = lane & 3;
    #pragma unroll
    for (int mt = 0; mt < 2; mt++) {
        const int row = bm + wm*32 + mt*16 + g;
        #pragma unroll
        for (int nt = 0; nt < 8; nt++) {
            const int col = bn + wn*64 + nt*8 + 2*tq;
            *(float2*)(C + (size_t)row * N + col) =
                make_float2(acc[mt][nt][0], acc[mt][nt][1]);
            *(float2*)(C + (size_t)(row + 8) * N + col) =
                make_float2(acc[mt][nt][2], acc[mt][nt][3]);
        }
    }
}

// ---------------------------------------------------------------------------
// fp32 -> (hi, lo) bf16, elementwise. n4 = elems/4.
// ---------------------------------------------------------------------------
__global__ void convert_hilo(const float4* __restrict__ in,
                             __nv_bfloat162* __restrict__ hi,
                             __nv_bfloat162* __restrict__ lo, int n4)
{
    int i = blockIdx.x * blockDim.x + threadIdx.x;
    if (i >= n4) return;
    float4 v = in[i];
    __nv_bfloat16 h0 = __float2bfloat16(v.x), h1 = __float2bfloat16(v.y);
    __nv_bfloat16 h2 = __float2bfloat16(v.z), h3 = __float2bfloat16(v.w);
    __nv_bfloat16 l0 = __float2bfloat16(v.x - __bfloat162float(h0));
    __nv_bfloat16 l1 = __float2bfloat16(v.y - __bfloat162float(h1));
    __nv_bfloat16 l2 = __float2bfloat16(v.z - __bfloat162float(h2));
    __nv_bfloat16 l3 = __float2bfloat16(v.w - __bfloat162float(h3));
    hi[2*i]   = __halves2bfloat162(h0, h1);
    hi[2*i+1] = __halves2bfloat162(h2, h3);
    lo[2*i]   = __halves2bfloat162(l0, l1);
    lo[2*i+1] = __halves2bfloat162(l2, l3);
}

// ---------------------------------------------------------------------------
// W[K,N] fp32 -> T[N,K] (hi, lo) bf16 (transpose + split). block (32,8).
// ---------------------------------------------------------------------------
__global__ void transpose_hilo(const float* __restrict__ W,
                               __nv_bfloat16* __restrict__ Thi,
                               __nv_bfloat16* __restrict__ Tlo, int K, int N)
{
    __shared__ float tile[32][33];
    const int n0 = blockIdx.x * 32, k0 = blockIdx.y * 32;
    const int tx = threadIdx.x, ty = threadIdx.y;
    #pragma unroll
    for (int j = 0; j < 4; j++)
        tile[ty + 8*j][tx] = W[(size_t)(k0 + ty + 8*j) * N + n0 + tx];
    __syncthreads();
    #pragma unroll
    for (int j = 0; j < 4; j++) {
        float v = tile[tx][ty + 8*j];
        __nv_bfloat16 h = __float2bfloat16(v);
        size_t o = (size_t)(n0 + ty + 8*j) * K + k0 + tx;
        Thi[o] = h;
        Tlo[o] = __float2bfloat16(v - __bfloat162float(h));
    }
}

// ---------------------------------------------------------------------------
// Fused masked attention (fp32) — epilogue now emits hi/lo bf16 directly.
// ---------------------------------------------------------------------------
__global__ __launch_bounds__(256) void attn_kernel(const float* __restrict__ qkv,
                                                   const float* __restrict__ span_params,
                                                   const float* __restrict__ stride_params,
                                                   __nv_bfloat16* __restrict__ yhi,
                                                   __nv_bfloat16* __restrict__ ylo)
{
    extern __shared__ float smf[];
    float* Qt   = smf;
    float* Kt   = smf + 4096;
    float* Vs   = smf + 8192;
    float* Pt   = smf + 12288;
    float* lred = smf + 16384;

    const int qt = blockIdx.x, h = blockIdx.y, b = blockIdx.z;
    const int t  = threadIdx.x;
    const int tx = t & 15, ty = t >> 4;
    const int i0 = qt * 64;

    const float sp = 1024.f / (1.f + __expf(-span_params[h]));
    const float p0 = stride_params[2*h], p1 = stride_params[2*h + 1];
    const float mxp = fmaxf(p0, p1);
    const float e0 = __expf(p0 - mxp), e1 = __expf(p1 - mxp);
    const float sw0 = e0 / (e0 + e1), sw1 = e1 / (e0 + e1);

    const float* base = qkv + (size_t)b * TT * N3C + h * THD;

    const int lr  = t >> 2;
    const int ld0 = (t & 3) << 4;

    {
        const float* src = base + (size_t)(i0 + lr) * N3C + ld0;
        #pragma unroll
        for (int i = 0; i < 16; i += 4) {
            float4 v = *(const float4*)(src + i);
            Qt[(ld0+i+0)*64 + lr] = v.x;
            Qt[(ld0+i+1)*64 + lr] = v.y;
            Qt[(ld0+i+2)*64 + lr] = v.z;
            Qt[(ld0+i+3)*64 + lr] = v.w;
        }
    }
    if (t < 64) lred[t] = 0.f;

    float accy[4][4] = {{0.f,0.f,0.f,0.f},{0.f,0.f,0.f,0.f},
                        {0.f,0.f,0.f,0.f},{0.f,0.f,0.f,0.f}};
    float accl[4] = {0.f, 0.f, 0.f, 0.f};

    int jt0 = (int)floorf(((float)i0 - 95.f - sp) * (1.f / 64.f)) + 1;
    if (jt0 < 0) jt0 = 0;

    for (int jt = jt0; jt <= qt; jt++) {
        {
            const float* ks = base + TC   + (size_t)(jt*64 + lr) * N3C + ld0;
            const float* vs = base + 2*TC + (size_t)(jt*64 + lr) * N3C + ld0;
            #pragma unroll
            for (int i = 0; i < 16; i += 4) {
                float4 kv = *(const float4*)(ks + i);
                Kt[(ld0+i+0)*64 + lr] = kv.x;
                Kt[(ld0+i+1)*64 + lr] = kv.y;
                Kt[(ld0+i+2)*64 + lr] = kv.z;
                Kt[(ld0+i+3)*64 + lr] = kv.w;
                float4 vv = *(const float4*)(vs + i);
                *(float4*)(&Vs[lr*64 + ld0 + i]) = vv;
            }
        }
        __syncthreads();

        float s[4][4] = {{0.f,0.f,0.f,0.f},{0.f,0.f,0.f,0.f},
                         {0.f,0.f,0.f,0.f},{0.f,0.f,0.f,0.f}};
        #pragma unroll 8
        for (int d = 0; d < 64; d++) {
            float4 a  = *(const float4*)(&Kt[d*64 + ty*4]);
            float4 bq = *(const float4*)(&Qt[d*64 + tx*4]);
            float ka[4] = {a.x, a.y, a.z, a.w};
            float qa[4] = {bq.x, bq.y, bq.z, bq.w};
            #pragma unroll
            for (int ik = 0; ik < 4; ik++)
                #pragma unroll
                for (int iq = 0; iq < 4; iq++)
                    s[ik][iq] = fmaf(ka[ik], qa[iq], s[ik][iq]);
        }

        #pragma unroll
        for (int ik = 0; ik < 4; ik++) {
            const int kglob = jt*64 + ty*4 + ik;
            float pr[4];
            #pragma unroll
            for (int iq = 0; iq < 4; iq++) {
                const int qglob = i0 + tx*4 + iq;
                const int rel = qglob - kglob;
                float p = 0.f;
                if (rel >= 0) {
                    float clipv = fminf(fmaxf((32.f + sp - (float)rel) * 0.03125f, 0.f), 1.f);
                    float mk = clipv * (sw0 + (((rel & 1) == 0) ? sw1 : 0.f));
                    p = __expf(s[ik][iq] * 0.125f) * mk;
                }
                pr[iq] = p;
                accl[iq] += p;
            }
            *(float4*)(&Pt[(ty*4 + ik)*64 + tx*4]) = make_float4(pr[0], pr[1], pr[2], pr[3]);
        }
        __syncthreads();

        #pragma unroll 8
        for (int kk = 0; kk < 64; kk++) {
            float4 a  = *(const float4*)(&Pt[kk*64 + ty*4]);
            float4 bv = *(const float4*)(&Vs[kk*64 + tx*4]);
            float pa[4] = {a.x, a.y, a.z, a.w};
            float va[4] = {bv.x, bv.y, bv.z, bv.w};
            #pragma unroll
            for (int iq = 0; iq < 4; iq++)
                #pragma unroll
                for (int id = 0; id < 4; id++)
                    accy[iq][id] = fmaf(pa[iq], va[id], accy[iq][id]);
        }
        __syncthreads();
    }

    #pragma unroll
    for (int iq = 0; iq < 4; iq++)
        atomicAdd(&lred[tx*4 + iq], accl[iq]);
    __syncthreads();

    // normalize + split hi/lo bf16 + store
    #pragma unroll
    for (int iq = 0; iq < 4; iq++) {
        const float inv = 1.f / lred[ty*4 + iq];
        const size_t off = (size_t)(b*TT + i0 + ty*4 + iq) * TC + h*THD + tx*4;
        __nv_bfloat16 hb[4], lb[4];
        #pragma unroll
        for (int id = 0; id < 4; id++) {
            float v = accy[iq][id] * inv;
            hb[id] = __float2bfloat16(v);
            lb[id] = __float2bfloat16(v - __bfloat162float(hb[id]));
        }
        *(__nv_bfloat162*)(yhi + off)     = __halves2bfloat162(hb[0], hb[1]);
        *(__nv_bfloat162*)(yhi + off + 2) = __halves2bfloat162(hb[2], hb[3]);
        *(__nv_bfloat162*)(ylo + off)     = __halves2bfloat162(lb[0], lb[1]);
        *(__nv_bfloat162*)(ylo + off + 2) = __halves2bfloat162(lb[2], lb[3]);
    }
}

// ---------------------------------------------------------------------------
__global__ void tail_kernel(const float* __restrict__ span_params,
                            float* __restrict__ out, int out_size)
{
    if (threadIdx.x == 0 && blockIdx.x == 0) {
        float s = 0.f;
        for (int i = 0; i < TH; i++)
            s += 1024.f / (1.f + expf(-span_params[i]));
        if (out_size > MR * TC)
            out[MR * TC] = 2e-6f * s / 16.f;
    }
}

extern "C" void kernel_launch(void* const* d_in, const int* in_sizes, int n_in,
                              void* d_out, int out_size)
{
    const float* x    = (const float*)d_in[0];
    const float* Wqkv = (const float*)d_in[1];
    const float* Wpr  = (const float*)d_in[2];
    const float* span = (const float*)d_in[3];
    const float* strd = (const float*)d_in[4];
    float* out = (float*)d_out;

    float *qkv_p;
    __nv_bfloat16 *xhi, *xlo, *wqh, *wql, *wph, *wpl, *yhi, *ylo;
    cudaGetSymbolAddress((void**)&qkv_p, g_qkv);
    cudaGetSymbolAddress((void**)&xhi, g_xhi);
    cudaGetSymbolAddress((void**)&xlo, g_xlo);
    cudaGetSymbolAddress((void**)&wqh, g_wqkv_hi);
    cudaGetSymbolAddress((void**)&wql, g_wqkv_lo);
    cudaGetSymbolAddress((void**)&wph, g_wpr_hi);
    cudaGetSymbolAddress((void**)&wpl, g_wpr_lo);
    cudaGetSymbolAddress((void**)&yhi, g_yhi);
    cudaGetSymbolAddress((void**)&ylo, g_ylo);

    static bool attr_set = false;
    const int attn_smem = (16384 + 64) * (int)sizeof(float);
    if (!attr_set) {
        cudaFuncSetAttribute(gemm_mma, cudaFuncAttributeMaxDynamicSharedMemorySize, GEMM_SMEM);
        cudaFuncSetAttribute(attn_kernel, cudaFuncAttributeMaxDynamicSharedMemorySize, attn_smem);
        attr_set = true;
    }

    // 0) operand prep: x -> hi/lo bf16 ; W -> transposed hi/lo bf16
    convert_hilo<<<(MR*TC/4 + 255)/256, 256>>>((const float4*)x,
        (__nv_bfloat162*)xhi, (__nv_bfloat162*)xlo, MR*TC/4);
    transpose_hilo<<<dim3(N3C/32, TC/32), dim3(32, 8)>>>(Wqkv, wqh, wql, TC, N3C);
    transpose_hilo<<<dim3(TC/32, TC/32), dim3(32, 8)>>>(Wpr, wph, wpl, TC, TC);

    // 1) qkv = x @ Wqkv  (split-bf16 mma.sync, 4-stage cp.async)
    gemm_mma<<<dim3(N3C/128, MR/128), 256, GEMM_SMEM>>>(xhi, xlo, wqh, wql,
                                                        qkv_p, MR, N3C, TC);

    // 2) fused masked attention -> yhi/ylo (split emitted in epilogue)
    attn_kernel<<<dim3(TT/64, TH, TB), 256, attn_smem>>>(qkv_p, span, strd, yhi, ylo);

    // 3) y = yatt @ Wproj -> d_out
    gemm_mma<<<dim3(TC/128, MR/128), 256, GEMM_SMEM>>>(yhi, ylo, wph, wpl,
                                                       out, MR, TC, TC);

    // 4) span_loss scalar
    tail_kernel<<<1, 32>>>(span, out, out_size);
}

// round 6
// speedup vs baseline: 1.0592x; 1.0592x over previous
#include <cuda_runtime.h>
#include <cuda_bf16.h>
#include <math.h>
#include <stdint.h>

#define TB 4
#define TT 1024
#define TC 1024
#define TH 16
#define THD 64
#define MR (TB*TT)          // 4096 rows
#define N3C (3*TC)          // 3072

// ---------------- scratch (allocation-free rule: device globals) -----------
static __device__ float g_qkv[(size_t)MR * N3C];     // 48 MB
static __device__ __nv_bfloat16 g_xhi[(size_t)MR * TC];
static __device__ __nv_bfloat16 g_xlo[(size_t)MR * TC];
static __device__ __nv_bfloat16 g_wqkv_hi[(size_t)N3C * TC];   // W^T [3072,1024]
static __device__ __nv_bfloat16 g_wqkv_lo[(size_t)N3C * TC];
static __device__ __nv_bfloat16 g_wpr_hi[(size_t)TC * TC];     // W^T [1024,1024]
static __device__ __nv_bfloat16 g_wpr_lo[(size_t)TC * TC];
static __device__ __nv_bfloat16 g_yhi[(size_t)MR * TC];
static __device__ __nv_bfloat16 g_ylo[(size_t)MR * TC];

// ---------------- PTX helpers (baseline ISA only) ---------------------------
__device__ __forceinline__ uint32_t smem_u32(const void* p) {
    uint32_t a;
    asm("{ .reg .u64 t; cvta.to.shared.u64 t, %1; cvt.u32.u64 %0, t; }" : "=r"(a) : "l"(p));
    return a;
}
__device__ __forceinline__ void ldsm_x4(uint32_t (&r)[4], uint32_t addr) {
    asm volatile("ldmatrix.sync.aligned.m8n8.x4.shared.b16 {%0,%1,%2,%3}, [%4];"
        : "=r"(r[0]), "=r"(r[1]), "=r"(r[2]), "=r"(r[3]) : "r"(addr));
}
__device__ __forceinline__ void mma_bf16(float (&d)[4], const uint32_t (&a)[4],
                                         uint32_t b0, uint32_t b1) {
    asm volatile("mma.sync.aligned.m16n8k16.row.col.f32.bf16.bf16.f32 "
        "{%0,%1,%2,%3}, {%4,%5,%6,%7}, {%8,%9}, {%0,%1,%2,%3};"
        : "+f"(d[0]), "+f"(d[1]), "+f"(d[2]), "+f"(d[3])
        : "r"(a[0]), "r"(a[1]), "r"(a[2]), "r"(a[3]), "r"(b0), "r"(b1));
}
__device__ __forceinline__ void cp_async16(uint32_t dst, const void* src) {
    asm volatile("cp.async.cg.shared.global [%0], [%1], 16;" :: "r"(dst), "l"(src) : "memory");
}
#define CP_COMMIT() asm volatile("cp.async.commit_group;" ::: "memory")
#define CP_WAIT2()  asm volatile("cp.async.wait_group 2;" ::: "memory")
#define CP_WAIT1()  asm volatile("cp.async.wait_group 1;" ::: "memory")
#define CP_WAIT0()  asm volatile("cp.async.wait_group 0;" ::: "memory")

// smem tile geometry: 128 rows x 24 bf16 (16 data + 8 pad -> conflict-free LDSM)
#define TROW 24
#define TILE_ELEMS (128*TROW)           // 3072 bf16
#define STAGE_ELEMS (4*TILE_ELEMS)      // Ah,Al,Bh,Bl = 12288 bf16
#define NSTAGE 4
#define GEMM_SMEM (NSTAGE*STAGE_ELEMS*2)  // 98304 bytes

// ---------------------------------------------------------------------------
// Split-bf16 tensor-core GEMM, 4-stage cp.async pipeline, single sync/iter,
// hard 2-CTA/SM occupancy (regs capped at 128 via launch_bounds):
//   C[M,N](fp32) = (Ahi+Alo) @ (Bhi+Blo)^T ; 3 products (lo*lo dropped).
// CTA 128x128, BK=16, 8 warps (4m x 2n), warp tile 32x64, mma.m16n8k16.
// ---------------------------------------------------------------------------
__global__ __launch_bounds__(256, 2) void gemm_mma(
    const __nv_bfloat16* __restrict__ Ahi, const __nv_bfloat16* __restrict__ Alo,
    const __nv_bfloat16* __restrict__ Bhi, const __nv_bfloat16* __restrict__ Blo,
    float* __restrict__ C, int M, int N, int K)
{
    extern __shared__ __nv_bfloat16 smem[];   // NSTAGE stages x 4 tiles

    const int t = threadIdx.x, lane = t & 31, wid = t >> 5;
    const int wm = wid & 3, wn = wid >> 2;
    const int bm = blockIdx.y * 128, bn = blockIdx.x * 128;

    float acc[2][8][4];
    #pragma unroll
    for (int i = 0; i < 2; i++)
        #pragma unroll
        for (int j = 0; j < 8; j++)
            #pragma unroll
            for (int k = 0; k < 4; k++) acc[i][j][k] = 0.f;

    // staging: 256 chunks (16B) per tile -> 1 chunk per thread per tile
    const int sr = t >> 1, scc = (t & 1) * 8;
    const __nv_bfloat16* gptr[4];
    gptr[0] = Ahi + (size_t)(bm + sr) * K + scc;
    gptr[1] = Alo + (size_t)(bm + sr) * K + scc;
    gptr[2] = Bhi + (size_t)(bn + sr) * K + scc;
    gptr[3] = Blo + (size_t)(bn + sr) * K + scc;
    uint32_t sdst[4];
    #pragma unroll
    for (int w = 0; w < 4; w++)
        sdst[w] = smem_u32(smem + w * TILE_ELEMS + sr * TROW + scc);
    const uint32_t stage_bytes = STAGE_ELEMS * 2;

    // LDSM lane addressing
    const int a_row = wm * 32 + (lane & 15);
    const int a_coff = (lane >> 4) * 8;
    const int b_row = wn * 64 + (lane & 7) + ((lane >> 4) & 1) * 8;
    const int b_coff = ((lane >> 3) & 1) * 8;

    const int niter = K >> 4;   // K/16

    // prologue: issue stages 0..2
    #pragma unroll
    for (int s = 0; s < NSTAGE - 1; s++) {
        const uint32_t soff = s * stage_bytes;
        #pragma unroll
        for (int w = 0; w < 4; w++)
            cp_async16(sdst[w] + soff, gptr[w] + (s << 4));
        CP_COMMIT();
    }

    for (int it = 0; it < niter; it++) {
        const int rem = niter - 1 - it;
        if (rem >= 2) CP_WAIT2(); else if (rem == 1) CP_WAIT1(); else CP_WAIT0();
        __syncthreads();

        // issue stage it+3 (overwrites buffer consumed in iter it-1)
        if (it + NSTAGE - 1 < niter) {
            const uint32_t soff = ((it + NSTAGE - 1) & (NSTAGE - 1)) * stage_bytes;
            const int kn = (it + NSTAGE - 1) << 4;
            #pragma unroll
            for (int w = 0; w < 4; w++)
                cp_async16(sdst[w] + soff, gptr[w] + kn);
            CP_COMMIT();
        }

        const __nv_bfloat16* bs = smem + (it & (NSTAGE - 1)) * STAGE_ELEMS;

        uint32_t ah[2][4], al[2][4];
        #pragma unroll
        for (int mt = 0; mt < 2; mt++) {
            ldsm_x4(ah[mt], smem_u32(bs + (a_row + mt*16) * TROW + a_coff));
            ldsm_x4(al[mt], smem_u32(bs + TILE_ELEMS + (a_row + mt*16) * TROW + a_coff));
        }

        #pragma unroll
        for (int np = 0; np < 4; np++) {
            uint32_t bh[4], bl[4];
            ldsm_x4(bh, smem_u32(bs + 2*TILE_ELEMS + (b_row + np*16) * TROW + b_coff));
            ldsm_x4(bl, smem_u32(bs + 3*TILE_ELEMS + (b_row + np*16) * TROW + b_coff));
            #pragma unroll
            for (int half = 0; half < 2; half++) {
                const int nt = np * 2 + half;
                #pragma unroll
                for (int mt = 0; mt < 2; mt++) {
                    mma_bf16(acc[mt][nt], ah[mt], bh[2*half], bh[2*half+1]);
                    mma_bf16(acc[mt][nt], ah[mt], bl[2*half], bl[2*half+1]);
                    mma_bf16(acc[mt][nt], al[mt], bh[2*half], bh[2*half+1]);
                }
            }
        }
    }

    // epilogue: D frag lane l -> rows (g, g+8), cols (2t, 2t+1)
    const int g = lane >> 2, tq = lane & 3;
    #pragma unroll
    for (int mt = 0; mt < 2; mt++) {
        const int row = bm + wm*32 + mt*16 + g;
        #pragma unroll
        for (int nt = 0; nt < 8; nt++) {
            const int col = bn + wn*64 + nt*8 + 2*tq;
            *(float2*)(C + (size_t)row * N + col) =
                make_float2(acc[mt][nt][0], acc[mt][nt][1]);
            *(float2*)(C + (size_t)(row + 8) * N + col) =
                make_float2(acc[mt][nt][2], acc[mt][nt][3]);
        }
    }
}

// ---------------------------------------------------------------------------
// fp32 -> (hi, lo) bf16, elementwise. n4 = elems/4.
// ---------------------------------------------------------------------------
__global__ void convert_hilo(const float4* __restrict__ in,
                             __nv_bfloat162* __restrict__ hi,
                             __nv_bfloat162* __restrict__ lo, int n4)
{
    int i = blockIdx.x * blockDim.x + threadIdx.x;
    if (i >= n4) return;
    float4 v = in[i];
    __nv_bfloat16 h0 = __float2bfloat16(v.x), h1 = __float2bfloat16(v.y);
    __nv_bfloat16 h2 = __float2bfloat16(v.z), h3 = __float2bfloat16(v.w);
    __nv_bfloat16 l0 = __float2bfloat16(v.x - __bfloat162float(h0));
    __nv_bfloat16 l1 = __float2bfloat16(v.y - __bfloat162float(h1));
    __nv_bfloat16 l2 = __float2bfloat16(v.z - __bfloat162float(h2));
    __nv_bfloat16 l3 = __float2bfloat16(v.w - __bfloat162float(h3));
    hi[2*i]   = __halves2bfloat162(h0, h1);
    hi[2*i+1] = __halves2bfloat162(h2, h3);
    lo[2*i]   = __halves2bfloat162(l0, l1);
    lo[2*i+1] = __halves2bfloat162(l2, l3);
}

// ---------------------------------------------------------------------------
// W[K,N] fp32 -> T[N,K] (hi, lo) bf16 (transpose + split). block (32,8).
// ---------------------------------------------------------------------------
__global__ void transpose_hilo(const float* __restrict__ W,
                               __nv_bfloat16* __restrict__ Thi,
                               __nv_bfloat16* __restrict__ Tlo, int K, int N)
{
    __shared__ float tile[32][33];
    const int n0 = blockIdx.x * 32, k0 = blockIdx.y * 32;
    const int tx = threadIdx.x, ty = threadIdx.y;
    #pragma unroll
    for (int j = 0; j < 4; j++)
        tile[ty + 8*j][tx] = W[(size_t)(k0 + ty + 8*j) * N + n0 + tx];
    __syncthreads();
    #pragma unroll
    for (int j = 0; j < 4; j++) {
        float v = tile[tx][ty + 8*j];
        __nv_bfloat16 h = __float2bfloat16(v);
        size_t o = (size_t)(n0 + ty + 8*j) * K + k0 + tx;
        Thi[o] = h;
        Tlo[o] = __float2bfloat16(v - __bfloat162float(h));
    }
}

// ---------------------------------------------------------------------------
// Fused masked attention (fp32) — epilogue emits hi/lo bf16 directly.
// ---------------------------------------------------------------------------
__global__ __launch_bounds__(256) void attn_kernel(const float* __restrict__ qkv,
                                                   const float* __restrict__ span_params,
                                                   const float* __restrict__ stride_params,
                                                   __nv_bfloat16* __restrict__ yhi,
                                                   __nv_bfloat16* __restrict__ ylo)
{
    extern __shared__ float smf[];
    float* Qt   = smf;
    float* Kt   = smf + 4096;
    float* Vs   = smf + 8192;
    float* Pt   = smf + 12288;
    float* lred = smf + 16384;

    const int qt = blockIdx.x, h = blockIdx.y, b = blockIdx.z;
    const int t  = threadIdx.x;
    const int tx = t & 15, ty = t >> 4;
    const int i0 = qt * 64;

    const float sp = 1024.f / (1.f + __expf(-span_params[h]));
    const float p0 = stride_params[2*h], p1 = stride_params[2*h + 1];
    const float mxp = fmaxf(p0, p1);
    const float e0 = __expf(p0 - mxp), e1 = __expf(p1 - mxp);
    const float sw0 = e0 / (e0 + e1), sw1 = e1 / (e0 + e1);

    const float* base = qkv + (size_t)b * TT * N3C + h * THD;

    const int lr  = t >> 2;
    const int ld0 = (t & 3) << 4;

    {
        const float* src = base + (size_t)(i0 + lr) * N3C + ld0;
        #pragma unroll
        for (int i = 0; i < 16; i += 4) {
            float4 v = *(const float4*)(src + i);
            Qt[(ld0+i+0)*64 + lr] = v.x;
            Qt[(ld0+i+1)*64 + lr] = v.y;
            Qt[(ld0+i+2)*64 + lr] = v.z;
            Qt[(ld0+i+3)*64 + lr] = v.w;
        }
    }
    if (t < 64) lred[t] = 0.f;

    float accy[4][4] = {{0.f,0.f,0.f,0.f},{0.f,0.f,0.f,0.f},
                        {0.f,0.f,0.f,0.f},{0.f,0.f,0.f,0.f}};
    float accl[4] = {0.f, 0.f, 0.f, 0.f};

    int jt0 = (int)floorf(((float)i0 - 95.f - sp) * (1.f / 64.f)) + 1;
    if (jt0 < 0) jt0 = 0;

    for (int jt = jt0; jt <= qt; jt++) {
        {
            const float* ks = base + TC   + (size_t)(jt*64 + lr) * N3C + ld0;
            const float* vs = base + 2*TC + (size_t)(jt*64 + lr) * N3C + ld0;
            #pragma unroll
            for (int i = 0; i < 16; i += 4) {
                float4 kv = *(const float4*)(ks + i);
                Kt[(ld0+i+0)*64 + lr] = kv.x;
                Kt[(ld0+i+1)*64 + lr] = kv.y;
                Kt[(ld0+i+2)*64 + lr] = kv.z;
                Kt[(ld0+i+3)*64 + lr] = kv.w;
                float4 vv = *(const float4*)(vs + i);
                *(float4*)(&Vs[lr*64 + ld0 + i]) = vv;
            }
        }
        __syncthreads();

        float s[4][4] = {{0.f,0.f,0.f,0.f},{0.f,0.f,0.f,0.f},
                         {0.f,0.f,0.f,0.f},{0.f,0.f,0.f,0.f}};
        #pragma unroll 8
        for (int d = 0; d < 64; d++) {
            float4 a  = *(const float4*)(&Kt[d*64 + ty*4]);
            float4 bq = *(const float4*)(&Qt[d*64 + tx*4]);
            float ka[4] = {a.x, a.y, a.z, a.w};
            float qa[4] = {bq.x, bq.y, bq.z, bq.w};
            #pragma unroll
            for (int ik = 0; ik < 4; ik++)
                #pragma unroll
                for (int iq = 0; iq < 4; iq++)
                    s[ik][iq] = fmaf(ka[ik], qa[iq], s[ik][iq]);
        }

        #pragma unroll
        for (int ik = 0; ik < 4; ik++) {
            const int kglob = jt*64 + ty*4 + ik;
            float pr[4];
            #pragma unroll
            for (int iq = 0; iq < 4; iq++) {
                const int qglob = i0 + tx*4 + iq;
                const int rel = qglob - kglob;
                float p = 0.f;
                if (rel >= 0) {
                    float clipv = fminf(fmaxf((32.f + sp - (float)rel) * 0.03125f, 0.f), 1.f);
                    float mk = clipv * (sw0 + (((rel & 1) == 0) ? sw1 : 0.f));
                    p = __expf(s[ik][iq] * 0.125f) * mk;
                }
                pr[iq] = p;
                accl[iq] += p;
            }
            *(float4*)(&Pt[(ty*4 + ik)*64 + tx*4]) = make_float4(pr[0], pr[1], pr[2], pr[3]);
        }
        __syncthreads();

        #pragma unroll 8
        for (int kk = 0; kk < 64; kk++) {
            float4 a  = *(const float4*)(&Pt[kk*64 + ty*4]);
            float4 bv = *(const float4*)(&Vs[kk*64 + tx*4]);
            float pa[4] = {a.x, a.y, a.z, a.w};
            float va[4] = {bv.x, bv.y, bv.z, bv.w};
            #pragma unroll
            for (int iq = 0; iq < 4; iq++)
                #pragma unroll
                for (int id = 0; id < 4; id++)
                    accy[iq][id] = fmaf(pa[iq], va[id], accy[iq][id]);
        }
        __syncthreads();
    }

    #pragma unroll
    for (int iq = 0; iq < 4; iq++)
        atomicAdd(&lred[tx*4 + iq], accl[iq]);
    __syncthreads();

    // normalize + split hi/lo bf16 + store
    #pragma unroll
    for (int iq = 0; iq < 4; iq++) {
        const float inv = 1.f / lred[ty*4 + iq];
        const size_t off = (size_t)(b*TT + i0 + ty*4 + iq) * TC + h*THD + tx*4;
        __nv_bfloat16 hb[4], lb[4];
        #pragma unroll
        for (int id = 0; id < 4; id++) {
            float v = accy[iq][id] * inv;
            hb[id] = __float2bfloat16(v);
            lb[id] = __float2bfloat16(v - __bfloat162float(hb[id]));
        }
        *(__nv_bfloat162*)(yhi + off)     = __halves2bfloat162(hb[0], hb[1]);
        *(__nv_bfloat162*)(yhi + off + 2) = __halves2bfloat162(hb[2], hb[3]);
        *(__nv_bfloat162*)(ylo + off)     = __halves2bfloat162(lb[0], lb[1]);
        *(__nv_bfloat162*)(ylo + off + 2) = __halves2bfloat162(lb[2], lb[3]);
    }
}

// ---------------------------------------------------------------------------
__global__ void tail_kernel(const float* __restrict__ span_params,
                            float* __restrict__ out, int out_size)
{
    if (threadIdx.x == 0 && blockIdx.x == 0) {
        float s = 0.f;
        for (int i = 0; i < TH; i++)
            s += 1024.f / (1.f + expf(-span_params[i]));
        if (out_size > MR * TC)
            out[MR * TC] = 2e-6f * s / 16.f;
    }
}

extern "C" void kernel_launch(void* const* d_in, const int* in_sizes, int n_in,
                              void* d_out, int out_size)
{
    const float* x    = (const float*)d_in[0];
    const float* Wqkv = (const float*)d_in[1];
    const float* Wpr  = (const float*)d_in[2];
    const float* span = (const float*)d_in[3];
    const float* strd = (const float*)d_in[4];
    float* out = (float*)d_out;

    float *qkv_p;
    __nv_bfloat16 *xhi, *xlo, *wqh, *wql, *wph, *wpl, *yhi, *ylo;
    cudaGetSymbolAddress((void**)&qkv_p, g_qkv);
    cudaGetSymbolAddress((void**)&xhi, g_xhi);
    cudaGetSymbolAddress((void**)&xlo, g_xlo);
    cudaGetSymbolAddress((void**)&wqh, g_wqkv_hi);
    cudaGetSymbolAddress((void**)&wql, g_wqkv_lo);
    cudaGetSymbolAddress((void**)&wph, g_wpr_hi);
    cudaGetSymbolAddress((void**)&wpl, g_wpr_lo);
    cudaGetSymbolAddress((void**)&yhi, g_yhi);
    cudaGetSymbolAddress((void**)&ylo, g_ylo);

    static bool attr_set = false;
    const int attn_smem = (16384 + 64) * (int)sizeof(float);
    if (!attr_set) {
        cudaFuncSetAttribute(gemm_mma, cudaFuncAttributeMaxDynamicSharedMemorySize, GEMM_SMEM);
        cudaFuncSetAttribute(attn_kernel, cudaFuncAttributeMaxDynamicSharedMemorySize, attn_smem);
        attr_set = true;
    }

    // 0) operand prep: x -> hi/lo bf16 ; W -> transposed hi/lo bf16
    convert_hilo<<<(MR*TC/4 + 255)/256, 256>>>((const float4*)x,
        (__nv_bfloat162*)xhi, (__nv_bfloat162*)xlo, MR*TC/4);
    transpose_hilo<<<dim3(N3C/32, TC/32), dim3(32, 8)>>>(Wqkv, wqh, wql, TC, N3C);
    transpose_hilo<<<dim3(TC/32, TC/32), dim3(32, 8)>>>(Wpr, wph, wpl, TC, TC);

    // 1) qkv = x @ Wqkv  (split-bf16 mma.sync, 4-stage cp.async, 2 CTA/SM)
    gemm_mma<<<dim3(N3C/128, MR/128), 256, GEMM_SMEM>>>(xhi, xlo, wqh, wql,
                                                        qkv_p, MR, N3C, TC);

    // 2) fused masked attention -> yhi/ylo (split emitted in epilogue)
    attn_kernel<<<dim3(TT/64, TH, TB), 256, attn_smem>>>(qkv_p, span, strd, yhi, ylo);

    // 3) y = yatt @ Wproj -> d_out
    gemm_mma<<<dim3(TC/128, MR/128), 256, GEMM_SMEM>>>(yhi, ylo, wph, wpl,
                                                       out, MR, TC, TC);

    // 4) span_loss scalar
    tail_kernel<<<1, 32>>>(span, out, out_size);
}

// round 7
// speedup vs baseline: 1.3842x; 1.3069x over previous
#include <cuda_runtime.h>
#include <cuda_bf16.h>
#include <math.h>
#include <stdint.h>

#define TB 4
#define TT 1024
#define TC 1024
#define TH 16
#define THD 64
#define MR (TB*TT)          // 4096 rows
#define N3C (3*TC)          // 3072

// ---------------- scratch (allocation-free rule: device globals) -----------
static __device__ __nv_bfloat16 g_qkvhi[(size_t)MR * N3C];   // 24 MB
static __device__ __nv_bfloat16 g_qkvlo[(size_t)MR * N3C];   // 24 MB
static __device__ __nv_bfloat16 g_xhi[(size_t)MR * TC];
static __device__ __nv_bfloat16 g_xlo[(size_t)MR * TC];
static __device__ __nv_bfloat16 g_wqkv_hi[(size_t)N3C * TC];   // W^T [3072,1024]
static __device__ __nv_bfloat16 g_wqkv_lo[(size_t)N3C * TC];
static __device__ __nv_bfloat16 g_wpr_hi[(size_t)TC * TC];     // W^T [1024,1024]
static __device__ __nv_bfloat16 g_wpr_lo[(size_t)TC * TC];
static __device__ __nv_bfloat16 g_yhi[(size_t)MR * TC];
static __device__ __nv_bfloat16 g_ylo[(size_t)MR * TC];

// ---------------- PTX helpers (baseline ISA only) ---------------------------
__device__ __forceinline__ uint32_t smem_u32(const void* p) {
    uint32_t a;
    asm("{ .reg .u64 t; cvta.to.shared.u64 t, %1; cvt.u32.u64 %0, t; }" : "=r"(a) : "l"(p));
    return a;
}
__device__ __forceinline__ void ldsm_x4(uint32_t (&r)[4], uint32_t addr) {
    asm volatile("ldmatrix.sync.aligned.m8n8.x4.shared.b16 {%0,%1,%2,%3}, [%4];"
        : "=r"(r[0]), "=r"(r[1]), "=r"(r[2]), "=r"(r[3]) : "r"(addr));
}
__device__ __forceinline__ void ldsm_x4t(uint32_t (&r)[4], uint32_t addr) {
    asm volatile("ldmatrix.sync.aligned.m8n8.x4.trans.shared.b16 {%0,%1,%2,%3}, [%4];"
        : "=r"(r[0]), "=r"(r[1]), "=r"(r[2]), "=r"(r[3]) : "r"(addr));
}
__device__ __forceinline__ void mma_bf16(float (&d)[4], const uint32_t (&a)[4],
                                         uint32_t b0, uint32_t b1) {
    asm volatile("mma.sync.aligned.m16n8k16.row.col.f32.bf16.bf16.f32 "
        "{%0,%1,%2,%3}, {%4,%5,%6,%7}, {%8,%9}, {%0,%1,%2,%3};"
        : "+f"(d[0]), "+f"(d[1]), "+f"(d[2]), "+f"(d[3])
        : "r"(a[0]), "r"(a[1]), "r"(a[2]), "r"(a[3]), "r"(b0), "r"(b1));
}
__device__ __forceinline__ void cp_async16(uint32_t dst, const void* src) {
    asm volatile("cp.async.cg.shared.global [%0], [%1], 16;" :: "r"(dst), "l"(src) : "memory");
}
#define CP_COMMIT() asm volatile("cp.async.commit_group;" ::: "memory")
#define CP_WAIT1()  asm volatile("cp.async.wait_group 1;" ::: "memory")
#define CP_WAIT0()  asm volatile("cp.async.wait_group 0;" ::: "memory")

// smem tile geometry for GEMM: 128 rows x 40 bf16 (32 data + 8 pad)
#define TROW 40
#define TILE_ELEMS (128*TROW)
#define STAGE_ELEMS (4*TILE_ELEMS)
#define GEMM_SMEM (2*STAGE_ELEMS*2)   // 2 stages, bytes

// ---------------------------------------------------------------------------
// Split-bf16 tensor-core GEMM (R4 mainloop), out_mode: 0 -> fp32 C,
// 1 -> bf16 hi/lo pair (Chi, Clo).
// ---------------------------------------------------------------------------
__global__ __launch_bounds__(256, 2) void gemm_mma(
    const __nv_bfloat16* __restrict__ Ahi, const __nv_bfloat16* __restrict__ Alo,
    const __nv_bfloat16* __restrict__ Bhi, const __nv_bfloat16* __restrict__ Blo,
    float* __restrict__ C, __nv_bfloat16* __restrict__ Chi,
    __nv_bfloat16* __restrict__ Clo, int out_mode, int M, int N, int K)
{
    extern __shared__ __nv_bfloat16 smem[];

    const int t = threadIdx.x, lane = t & 31, wid = t >> 5;
    const int wm = wid & 3, wn = wid >> 2;
    const int bm = blockIdx.y * 128, bn = blockIdx.x * 128;

    float acc[2][8][4];
    #pragma unroll
    for (int i = 0; i < 2; i++)
        #pragma unroll
        for (int j = 0; j < 8; j++)
            #pragma unroll
            for (int k = 0; k < 4; k++) acc[i][j][k] = 0.f;

    // staging: 512 16B chunks per tile, 2 per thread
    const int c0 = t * 2;
    const int r0 = c0 >> 2,       cc0 = (c0 & 3) * 8;
    const int r1 = (c0 + 1) >> 2, cc1 = ((c0 + 1) & 3) * 8;
    const __nv_bfloat16* g0[4];
    const __nv_bfloat16* g1[4];
    g0[0] = Ahi + (size_t)(bm + r0) * K + cc0;  g1[0] = Ahi + (size_t)(bm + r1) * K + cc1;
    g0[1] = Alo + (size_t)(bm + r0) * K + cc0;  g1[1] = Alo + (size_t)(bm + r1) * K + cc1;
    g0[2] = Bhi + (size_t)(bn + r0) * K + cc0;  g1[2] = Bhi + (size_t)(bn + r1) * K + cc1;
    g0[3] = Blo + (size_t)(bn + r0) * K + cc0;  g1[3] = Blo + (size_t)(bn + r1) * K + cc1;
    uint32_t s0[4], s1[4];
    #pragma unroll
    for (int w = 0; w < 4; w++) {
        s0[w] = smem_u32(smem + w * TILE_ELEMS + r0 * TROW + cc0);
        s1[w] = smem_u32(smem + w * TILE_ELEMS + r1 * TROW + cc1);
    }
    const uint32_t stage_bytes = STAGE_ELEMS * 2;

    const int a_row = wm * 32 + (lane & 15);
    const int a_coff = (lane >> 4) * 8;
    const int b_row = wn * 64 + (lane & 7) + ((lane >> 4) & 1) * 8;
    const int b_coff = ((lane >> 3) & 1) * 8;

    const int niter = K >> 5;

    #pragma unroll
    for (int w = 0; w < 4; w++) { cp_async16(s0[w], g0[w]); cp_async16(s1[w], g1[w]); }
    CP_COMMIT();

    for (int it = 0; it < niter; it++) {
        if (it + 1 < niter) {
            const int kn = (it + 1) << 5;
            const uint32_t soff = ((it + 1) & 1) * stage_bytes;
            #pragma unroll
            for (int w = 0; w < 4; w++) {
                cp_async16(s0[w] + soff, g0[w] + kn);
                cp_async16(s1[w] + soff, g1[w] + kn);
            }
            CP_COMMIT();
            CP_WAIT1();
        } else {
            CP_WAIT0();
        }
        __syncthreads();

        const __nv_bfloat16* bs = smem + (it & 1) * STAGE_ELEMS;
        #pragma unroll
        for (int ks = 0; ks < 2; ks++) {
            uint32_t ah[2][4], al[2][4];
            #pragma unroll
            for (int mt = 0; mt < 2; mt++) {
                ldsm_x4(ah[mt], smem_u32(bs + (a_row + mt*16) * TROW + ks*16 + a_coff));
                ldsm_x4(al[mt], smem_u32(bs + TILE_ELEMS + (a_row + mt*16) * TROW + ks*16 + a_coff));
            }
            #pragma unroll
            for (int np = 0; np < 4; np++) {
                uint32_t bh[4], bl[4];
                ldsm_x4(bh, smem_u32(bs + 2*TILE_ELEMS + (b_row + np*16) * TROW + ks*16 + b_coff));
                ldsm_x4(bl, smem_u32(bs + 3*TILE_ELEMS + (b_row + np*16) * TROW + ks*16 + b_coff));
                #pragma unroll
                for (int half = 0; half < 2; half++) {
                    const int nt = np * 2 + half;
                    #pragma unroll
                    for (int mt = 0; mt < 2; mt++) {
                        mma_bf16(acc[mt][nt], ah[mt], bh[2*half], bh[2*half+1]);
                        mma_bf16(acc[mt][nt], ah[mt], bl[2*half], bl[2*half+1]);
                        mma_bf16(acc[mt][nt], al[mt], bh[2*half], bh[2*half+1]);
                    }
                }
            }
        }
        __syncthreads();
    }

    const int g = lane >> 2, tq = lane & 3;
    #pragma unroll
    for (int mt = 0; mt < 2; mt++) {
        const int row = bm + wm*32 + mt*16 + g;
        #pragma unroll
        for (int nt = 0; nt < 8; nt++) {
            const int col = bn + wn*64 + nt*8 + 2*tq;
            if (out_mode == 0) {
                *(float2*)(C + (size_t)row * N + col) =
                    make_float2(acc[mt][nt][0], acc[mt][nt][1]);
                *(float2*)(C + (size_t)(row + 8) * N + col) =
                    make_float2(acc[mt][nt][2], acc[mt][nt][3]);
            } else {
                #pragma unroll
                for (int rr = 0; rr < 2; rr++) {
                    const float v0 = acc[mt][nt][2*rr], v1 = acc[mt][nt][2*rr+1];
                    const __nv_bfloat16 h0 = __float2bfloat16(v0);
                    const __nv_bfloat16 h1 = __float2bfloat16(v1);
                    const __nv_bfloat16 l0 = __float2bfloat16(v0 - __bfloat162float(h0));
                    const __nv_bfloat16 l1 = __float2bfloat16(v1 - __bfloat162float(h1));
                    const size_t off = (size_t)(row + 8*rr) * N + col;
                    *(__nv_bfloat162*)(Chi + off) = __halves2bfloat162(h0, h1);
                    *(__nv_bfloat162*)(Clo + off) = __halves2bfloat162(l0, l1);
                }
            }
        }
    }
}

// ---------------------------------------------------------------------------
// fp32 -> (hi, lo) bf16, elementwise.
// ---------------------------------------------------------------------------
__global__ void convert_hilo(const float4* __restrict__ in,
                             __nv_bfloat162* __restrict__ hi,
                             __nv_bfloat162* __restrict__ lo, int n4)
{
    int i = blockIdx.x * blockDim.x + threadIdx.x;
    if (i >= n4) return;
    float4 v = in[i];
    __nv_bfloat16 h0 = __float2bfloat16(v.x), h1 = __float2bfloat16(v.y);
    __nv_bfloat16 h2 = __float2bfloat16(v.z), h3 = __float2bfloat16(v.w);
    __nv_bfloat16 l0 = __float2bfloat16(v.x - __bfloat162float(h0));
    __nv_bfloat16 l1 = __float2bfloat16(v.y - __bfloat162float(h1));
    __nv_bfloat16 l2 = __float2bfloat16(v.z - __bfloat162float(h2));
    __nv_bfloat16 l3 = __float2bfloat16(v.w - __bfloat162float(h3));
    hi[2*i]   = __halves2bfloat162(h0, h1);
    hi[2*i+1] = __halves2bfloat162(h2, h3);
    lo[2*i]   = __halves2bfloat162(l0, l1);
    lo[2*i+1] = __halves2bfloat162(l2, l3);
}

// ---------------------------------------------------------------------------
// W[K,N] fp32 -> T[N,K] (hi, lo) bf16 (transpose + split).
// ---------------------------------------------------------------------------
__global__ void transpose_hilo(const float* __restrict__ W,
                               __nv_bfloat16* __restrict__ Thi,
                               __nv_bfloat16* __restrict__ Tlo, int K, int N)
{
    __shared__ float tile[32][33];
    const int n0 = blockIdx.x * 32, k0 = blockIdx.y * 32;
    const int tx = threadIdx.x, ty = threadIdx.y;
    #pragma unroll
    for (int j = 0; j < 4; j++)
        tile[ty + 8*j][tx] = W[(size_t)(k0 + ty + 8*j) * N + n0 + tx];
    __syncthreads();
    #pragma unroll
    for (int j = 0; j < 4; j++) {
        float v = tile[tx][ty + 8*j];
        __nv_bfloat16 h = __float2bfloat16(v);
        size_t o = (size_t)(n0 + ty + 8*j) * K + k0 + tx;
        Thi[o] = h;
        Tlo[o] = __float2bfloat16(v - __bfloat162float(h));
    }
}

// ---------------------------------------------------------------------------
// Tensor-core flash attention. CTA = (64-q-tile, head, batch), 4 warps,
// warp = 16 q-rows. S and P·V via 3-product split-bf16 mma; mask+exp in
// register fragments; P reused as A-fragment without smem round trip.
// smem rows padded to 72 bf16 (144 B) -> conflict-free ldmatrix.
// ---------------------------------------------------------------------------
#define ASQ 72
#define ATILE (64*ASQ)          // elems per smem tile
#define ATTN_SMEM (6*ATILE*2)   // Qh,Ql,Kh,Kl,Vh,Vl bytes = 55296

__global__ __launch_bounds__(128) void attn_mma(
    const __nv_bfloat16* __restrict__ qkvhi, const __nv_bfloat16* __restrict__ qkvlo,
    const float* __restrict__ span_params, const float* __restrict__ stride_params,
    __nv_bfloat16* __restrict__ yhi, __nv_bfloat16* __restrict__ ylo)
{
    extern __shared__ __nv_bfloat16 sm[];
    __nv_bfloat16* Qh = sm;
    __nv_bfloat16* Ql = sm + ATILE;
    __nv_bfloat16* Kh = sm + 2*ATILE;
    __nv_bfloat16* Kl = sm + 3*ATILE;
    __nv_bfloat16* Vh = sm + 4*ATILE;
    __nv_bfloat16* Vl = sm + 5*ATILE;

    const int qt = blockIdx.x, h = blockIdx.y, b = blockIdx.z;
    const int t = threadIdx.x, lane = t & 31, w = t >> 5;
    const int i0 = qt * 64;

    const float sp = 1024.f / (1.f + __expf(-span_params[h]));
    const float p0 = stride_params[2*h], p1 = stride_params[2*h + 1];
    const float mxp = fmaxf(p0, p1);
    const float e0 = __expf(p0 - mxp), e1 = __expf(p1 - mxp);
    const float sw0 = e0 / (e0 + e1), sw1 = e1 / (e0 + e1);
    const float c1 = 32.f + sp;     // clip numerator base

    // ---- load Q tile (64 x 64) hi/lo ----
    const int lr = t >> 1, lc = (t & 1) * 32;
    {
        const size_t gq = (size_t)(b*TT + i0 + lr) * N3C + h*THD + lc;
        #pragma unroll
        for (int i = 0; i < 4; i++) {
            *(uint4*)(Qh + lr*ASQ + lc + i*8) = *(const uint4*)(qkvhi + gq + i*8);
            *(uint4*)(Ql + lr*ASQ + lc + i*8) = *(const uint4*)(qkvlo + gq + i*8);
        }
    }
    __syncthreads();

    // ---- Q fragments (held for whole kernel) ----
    uint32_t qfh[4][4], qfl[4][4];
    {
        const int a_row = w*16 + (lane & 15);
        const int a_coff = (lane >> 4) * 8;
        #pragma unroll
        for (int ks = 0; ks < 4; ks++) {
            ldsm_x4(qfh[ks], smem_u32(Qh + a_row*ASQ + ks*16 + a_coff));
            ldsm_x4(qfl[ks], smem_u32(Ql + a_row*ASQ + ks*16 + a_coff));
        }
    }

    float accy[8][4];
    #pragma unroll
    for (int i = 0; i < 8; i++)
        #pragma unroll
        for (int j = 0; j < 4; j++) accy[i][j] = 0.f;
    float rs0 = 0.f, rs1 = 0.f;

    const int g = lane >> 2, tq2 = (lane & 3) * 2;
    const int q0 = i0 + w*16 + g;         // row for c0,c1
    // ldsm addresses (row/col parts)
    const int kb_row = (lane & 7) + ((lane >> 4) & 1) * 8;
    const int kb_coff = ((lane >> 3) & 1) * 8;
    const int vb_row = (lane & 7) + ((lane >> 3) & 1) * 8;
    const int vb_coff = (lane >> 4) * 8;

    int jt0 = (int)floorf(((float)i0 - 95.f - sp) * (1.f / 64.f)) + 1;
    if (jt0 < 0) jt0 = 0;

    for (int jt = jt0; jt <= qt; jt++) {
        __syncthreads();   // previous iteration's fragment reads done
        // ---- load K,V tiles hi/lo ----
        {
            const size_t gk = (size_t)(b*TT + jt*64 + lr) * N3C + TC   + h*THD + lc;
            const size_t gv = (size_t)(b*TT + jt*64 + lr) * N3C + 2*TC + h*THD + lc;
            #pragma unroll
            for (int i = 0; i < 4; i++) {
                *(uint4*)(Kh + lr*ASQ + lc + i*8) = *(const uint4*)(qkvhi + gk + i*8);
                *(uint4*)(Kl + lr*ASQ + lc + i*8) = *(const uint4*)(qkvlo + gk + i*8);
                *(uint4*)(Vh + lr*ASQ + lc + i*8) = *(const uint4*)(qkvhi + gv + i*8);
                *(uint4*)(Vl + lr*ASQ + lc + i*8) = *(const uint4*)(qkvlo + gv + i*8);
            }
        }
        __syncthreads();

        // ---- S = Q K^T (3-product) ----
        float s[8][4];
        #pragma unroll
        for (int i = 0; i < 8; i++)
            #pragma unroll
            for (int j = 0; j < 4; j++) s[i][j] = 0.f;
        #pragma unroll
        for (int np = 0; np < 4; np++) {
            #pragma unroll
            for (int ks = 0; ks < 4; ks++) {
                uint32_t bh[4], bl[4];
                ldsm_x4(bh, smem_u32(Kh + (np*16 + kb_row)*ASQ + ks*16 + kb_coff));
                ldsm_x4(bl, smem_u32(Kl + (np*16 + kb_row)*ASQ + ks*16 + kb_coff));
                #pragma unroll
                for (int half = 0; half < 2; half++) {
                    const int nf = np*2 + half;
                    mma_bf16(s[nf], qfh[ks], bh[2*half], bh[2*half+1]);
                    mma_bf16(s[nf], qfh[ks], bl[2*half], bl[2*half+1]);
                    mma_bf16(s[nf], qfl[ks], bh[2*half], bh[2*half+1]);
                }
            }
        }

        // ---- mask + exp + rowsum + pack P (hi/lo) ----
        uint32_t pfh[4][4], pfl[4][4];
        #pragma unroll
        for (int nf = 0; nf < 8; nf++) {
            const int kk = jt*64 + nf*8 + tq2;
            float pv[4];
            #pragma unroll
            for (int e = 0; e < 4; e++) {
                const int qq = q0 + (e >> 1) * 8;
                const int kc = kk + (e & 1);
                const int rel = qq - kc;
                float p = 0.f;
                if (rel >= 0) {
                    float clip = fminf(fmaxf((c1 - (float)rel) * 0.03125f, 0.f), 1.f);
                    float mk = clip * (sw0 + (((rel & 1) == 0) ? sw1 : 0.f));
                    p = __expf(s[nf][e] * 0.125f) * mk;
                }
                pv[e] = p;
            }
            rs0 += pv[0] + pv[1];
            rs1 += pv[2] + pv[3];
            __nv_bfloat16 hh[4], ll[4];
            #pragma unroll
            for (int e = 0; e < 4; e++) {
                hh[e] = __float2bfloat16(pv[e]);
                ll[e] = __float2bfloat16(pv[e] - __bfloat162float(hh[e]));
            }
            const int j = nf >> 1, odd = nf & 1;
            uint32_t ph01, ph23, pl01, pl23;
            memcpy(&ph01, &hh[0], 4); memcpy(&ph23, &hh[2], 4);
            memcpy(&pl01, &ll[0], 4); memcpy(&pl23, &ll[2], 4);
            pfh[j][2*odd]   = ph01;  pfh[j][2*odd+1] = ph23;
            pfl[j][2*odd]   = pl01;  pfl[j][2*odd+1] = pl23;
        }

        // ---- Y += P V (3-product), V fragments via ldmatrix.trans ----
        #pragma unroll
        for (int dnp = 0; dnp < 4; dnp++) {
            #pragma unroll
            for (int ks = 0; ks < 4; ks++) {
                uint32_t vh[4], vl[4];
                ldsm_x4t(vh, smem_u32(Vh + (ks*16 + vb_row)*ASQ + dnp*16 + vb_coff));
                ldsm_x4t(vl, smem_u32(Vl + (ks*16 + vb_row)*ASQ + dnp*16 + vb_coff));
                #pragma unroll
                for (int half = 0; half < 2; half++) {
                    const int df = dnp*2 + half;
                    mma_bf16(accy[df], pfh[ks], vh[2*half], vh[2*half+1]);
                    mma_bf16(accy[df], pfh[ks], vl[2*half], vl[2*half+1]);
                    mma_bf16(accy[df], pfl[ks], vh[2*half], vh[2*half+1]);
                }
            }
        }
    }

    // ---- rowsum reduction over quad, normalize, emit hi/lo ----
    rs0 += __shfl_xor_sync(0xffffffffu, rs0, 1);
    rs0 += __shfl_xor_sync(0xffffffffu, rs0, 2);
    rs1 += __shfl_xor_sync(0xffffffffu, rs1, 1);
    rs1 += __shfl_xor_sync(0xffffffffu, rs1, 2);
    const float inv0 = 1.f / rs0, inv1 = 1.f / rs1;

    const size_t row0 = (size_t)(b*TT + i0 + w*16 + g);
    #pragma unroll
    for (int df = 0; df < 8; df++) {
        const int col = h*THD + df*8 + tq2;
        #pragma unroll
        for (int rr = 0; rr < 2; rr++) {
            const float inv = rr ? inv1 : inv0;
            const float v0 = accy[df][2*rr] * inv, v1 = accy[df][2*rr+1] * inv;
            const __nv_bfloat16 h0 = __float2bfloat16(v0);
            const __nv_bfloat16 h1 = __float2bfloat16(v1);
            const __nv_bfloat16 l0 = __float2bfloat16(v0 - __bfloat162float(h0));
            const __nv_bfloat16 l1 = __float2bfloat16(v1 - __bfloat162float(h1));
            const size_t off = (row0 + 8*rr) * TC + col;
            *(__nv_bfloat162*)(yhi + off) = __halves2bfloat162(h0, h1);
            *(__nv_bfloat162*)(ylo + off) = __halves2bfloat162(l0, l1);
        }
    }
}

// ---------------------------------------------------------------------------
__global__ void tail_kernel(const float* __restrict__ span_params,
                            float* __restrict__ out, int out_size)
{
    if (threadIdx.x == 0 && blockIdx.x == 0) {
        float s = 0.f;
        for (int i = 0; i < TH; i++)
            s += 1024.f / (1.f + expf(-span_params[i]));
        if (out_size > MR * TC)
            out[MR * TC] = 2e-6f * s / 16.f;
    }
}

extern "C" void kernel_launch(void* const* d_in, const int* in_sizes, int n_in,
                              void* d_out, int out_size)
{
    const float* x    = (const float*)d_in[0];
    const float* Wqkv = (const float*)d_in[1];
    const float* Wpr  = (const float*)d_in[2];
    const float* span = (const float*)d_in[3];
    const float* strd = (const float*)d_in[4];
    float* out = (float*)d_out;

    __nv_bfloat16 *qkvhi, *qkvlo, *xhi, *xlo, *wqh, *wql, *wph, *wpl, *yhi, *ylo;
    cudaGetSymbolAddress((void**)&qkvhi, g_qkvhi);
    cudaGetSymbolAddress((void**)&qkvlo, g_qkvlo);
    cudaGetSymbolAddress((void**)&xhi, g_xhi);
    cudaGetSymbolAddress((void**)&xlo, g_xlo);
    cudaGetSymbolAddress((void**)&wqh, g_wqkv_hi);
    cudaGetSymbolAddress((void**)&wql, g_wqkv_lo);
    cudaGetSymbolAddress((void**)&wph, g_wpr_hi);
    cudaGetSymbolAddress((void**)&wpl, g_wpr_lo);
    cudaGetSymbolAddress((void**)&yhi, g_yhi);
    cudaGetSymbolAddress((void**)&ylo, g_ylo);

    static bool attr_set = false;
    if (!attr_set) {
        cudaFuncSetAttribute(gemm_mma, cudaFuncAttributeMaxDynamicSharedMemorySize, GEMM_SMEM);
        cudaFuncSetAttribute(attn_mma, cudaFuncAttributeMaxDynamicSharedMemorySize, ATTN_SMEM);
        attr_set = true;
    }

    // 0) operand prep
    convert_hilo<<<(MR*TC/4 + 255)/256, 256>>>((const float4*)x,
        (__nv_bfloat162*)xhi, (__nv_bfloat162*)xlo, MR*TC/4);
    transpose_hilo<<<dim3(N3C/32, TC/32), dim3(32, 8)>>>(Wqkv, wqh, wql, TC, N3C);
    transpose_hilo<<<dim3(TC/32, TC/32), dim3(32, 8)>>>(Wpr, wph, wpl, TC, TC);

    // 1) qkv = x @ Wqkv -> bf16 hi/lo directly
    gemm_mma<<<dim3(N3C/128, MR/128), 256, GEMM_SMEM>>>(xhi, xlo, wqh, wql,
        nullptr, qkvhi, qkvlo, 1, MR, N3C, TC);

    // 2) tensor-core flash attention -> yhi/ylo
    attn_mma<<<dim3(TT/64, TH, TB), 128, ATTN_SMEM>>>(qkvhi, qkvlo, span, strd, yhi, ylo);

    // 3) y = yatt @ Wproj -> d_out (fp32)
    gemm_mma<<<dim3(TC/128, MR/128), 256, GEMM_SMEM>>>(yhi, ylo, wph, wpl,
        out, nullptr, nullptr, 0, MR, TC, TC);

    // 4) span_loss scalar
    tail_kernel<<<1, 32>>>(span, out, out_size);
}